// round 15
// baseline (speedup 1.0000x reference)
#include <cuda_runtime.h>
#include <cuda_bf16.h>
#include <math.h>

#define Bsz   16
#define CH    32
#define DCH   3
#define S     128
#define HH    255
#define WW    255
#define WP    256
#define NPIX  (HH*WW)
#define M12   12
#define KX24  24
#define ROWS  (Bsz*CH*HH)          // 130560
#define BN_EPS 1e-5f

typedef unsigned long long ull;

__device__ __forceinline__ ull pack2(float lo, float hi) {
    ull r; asm("mov.b64 %0, {%1,%2};" : "=l"(r) : "f"(lo), "f"(hi)); return r;
}
__device__ __forceinline__ void unpack2(ull v, float& lo, float& hi) {
    asm("mov.b64 {%0,%1}, %2;" : "=f"(lo), "=f"(hi) : "l"(v));
}
__device__ __forceinline__ ull ffma2(ull a, ull b, ull c) {
    ull d; asm("fma.rn.f32x2 %0, %1, %2, %3;" : "=l"(d) : "l"(a), "l"(b), "l"(c)); return d;
}
__device__ __forceinline__ ull fadd2(ull a, ull b) {
    ull d; asm("add.rn.f32x2 %0, %1, %2;" : "=l"(d) : "l"(a), "l"(b)); return d;
}

// ---------------- scratch ----------------
__device__ __align__(16) float  g_h[Bsz*CH*HH*WP];
__device__ __align__(16) float  g_t[Bsz*CH*HH*WP];
__device__ __align__(16) float2 g_Y [ROWS*M12];
__device__ __align__(16) float2 g_Z [Bsz*CH*KX24*M12];
__device__ __align__(16) float2 g_Zm[Bsz*CH*KX24*M12];
__device__ __align__(16) float2 g_Yi[ROWS*M12];
__device__ __align__(16) float2 g_ET[13*256];   // (cos, -sin)(2pi k t/255); t=255 -> 0
__device__ __align__(16) float  g_Ec[13*256];   // cos
__device__ __align__(16) float  g_Es[13*256];   // sin
__device__ float  g_sum[CH], g_sumsq[CH];
__device__ float  g_scale[CH], g_shift[CH];

// ---------------- init ----------------
__global__ void k_init() {
    int t = blockIdx.x * blockDim.x + threadIdx.x;
    if (t < 13*256) {
        int k = t >> 8, w = t & 255;
        float c = 0.f, s = 0.f;
        if (w < 255) {
            int m = (k * w) % 255;
            float a = 2.0f * (float)m / 255.0f;
            c = cospif(a); s = sinpif(a);
        }
        g_ET[t] = make_float2(c, -s);
        g_Ec[t] = c;
        g_Es[t] = s;
    }
    if (t < CH) { g_sum[t] = 0.f; g_sumsq[t] = 0.f; }
}

// ---------------- K0: mirror + fc0 ----------------
__global__ void k0_fc0(const float* __restrict__ x,
                       const float* __restrict__ fc0_w,
                       const float* __restrict__ fc0_b) {
    __shared__ float sW[DCH*CH];
    __shared__ float sB[CH];
    if (threadIdx.x < DCH*CH) sW[threadIdx.x] = fc0_w[threadIdx.x];
    if (threadIdx.x < CH)     sB[threadIdx.x] = fc0_b[threadIdx.x];
    __syncthreads();

    int g = blockIdx.x * blockDim.x + threadIdx.x;
    if (g >= Bsz * NPIX) return;
    int b = g / NPIX, p = g % NPIX;
    int i = p / WW, j = p % WW;
    int sr = (i < S-1) ? (S-1 - i) : (i - (S-1));
    int sc = (j < S-1) ? (S-1 - j) : (j - (S-1));
    float sign = ((i < S-1) == (j < S-1)) ? 1.0f : -1.0f;

    float v[DCH];
#pragma unroll
    for (int c = 0; c < DCH; c++)
        v[c] = sign * x[((b*DCH + c)*S + sr)*S + sc];

#pragma unroll
    for (int d = 0; d < CH; d++) {
        float acc = sB[d];
#pragma unroll
        for (int c = 0; c < DCH; c++) acc += v[c] * sW[c*CH + d];
        g_h[((size_t)(b*CH + d)*HH + i)*WP + j] = acc;
    }
}

// ---------------- K1: forward DFT along w; thread = (4-row group, mode, half) ----------------
__global__ __launch_bounds__(192) void k1_fwd_w(int prev_bn) {
    __shared__ float sX[32*260];
    __shared__ ull   sRed[192*4];
    int tid = threadIdx.x;
    const float* src = prev_bn ? g_t : g_h;
    int r0 = blockIdx.x * 32;
    for (int t = tid; t < 32*64; t += 192) {
        int rl = t >> 6, seg = t & 63;
        int rg = r0 + rl;
        float4 v = *(const float4*)&src[(size_t)rg*WP + seg*4];
        if (prev_bn) {
            int c = (rg / HH) & (CH-1);
            float scl = g_scale[c], shf = g_shift[c];
            v.x = fmaxf(v.x*scl + shf, 0.f);
            v.y = fmaxf(v.y*scl + shf, 0.f);
            v.z = fmaxf(v.z*scl + shf, 0.f);
            v.w = fmaxf(v.w*scl + shf, 0.f);
        }
        if (seg == 63) v.w = 0.f;              // pad col 255
        *(float4*)&sX[rl*260 + seg*4] = v;
    }
    __syncthreads();

    int half = tid & 1, k = (tid >> 1) % 12, g = tid / 24;
    const ull* gE = (const ull*)g_ET + k*256 + half*128;
    const float* x0 = sX + (4*g)*260 + half*128;

    ull a0 = 0, a1 = 0, a2 = 0, a3 = 0;
#pragma unroll 4
    for (int i = 0; i < 128; i++) {
        ull e = __ldg(gE + i);
        float x1v = x0[i], x2v = x0[260 + i], x3v = x0[520 + i], x4v = x0[780 + i];
        a0 = ffma2(e, pack2(x1v, x1v), a0);
        a1 = ffma2(e, pack2(x2v, x2v), a1);
        a2 = ffma2(e, pack2(x3v, x3v), a2);
        a3 = ffma2(e, pack2(x4v, x4v), a3);
    }
    sRed[tid*4 + 0] = a0; sRed[tid*4 + 1] = a1;
    sRed[tid*4 + 2] = a2; sRed[tid*4 + 3] = a3;
    __syncthreads();
    if (half == 0) {
        const ull* p = &sRed[(tid + 1)*4];
        ull* outp = (ull*)g_Y + (size_t)(r0 + 4*g)*M12 + k;
        outp[0]      = fadd2(a0, p[0]);
        outp[M12]    = fadd2(a1, p[1]);
        outp[2*M12]  = fadd2(a2, p[2]);
        outp[3*M12]  = fadd2(a3, p[3]);
    }
}

// ---------------- K2: forward DFT along h; conjugate-pair trick ----------------
// kr 0..11 -> z+ into Z[kr] (kx = kr); kr 1..12 -> z- into Z[24-kr] (kx = 255-kr).
__global__ __launch_bounds__(160) void k2_fwd_h() {
    __shared__ float2 sY[HH*M12];
    int bc = blockIdx.x, tid = threadIdx.x;
    const float2* Yg = g_Y + (size_t)bc*HH*M12;
    for (int t = tid; t < HH*M12; t += 160) sY[t] = Yg[t];
    __syncthreads();
    if (tid >= 156) return;

    int ky = tid % 12, kr = tid / 12;       // kr 0..12
    const ull* gE = (const ull*)g_ET + kr*256;
    ull pt = 0, rq = 0;                     // (P,-T), (R,-Q)
#pragma unroll 4
    for (int h = 0; h < HH; h++) {
        float2 y = sY[h*M12 + ky];
        ull e = __ldg(gE + h);
        pt = ffma2(e, pack2(y.x, y.x), pt);
        rq = ffma2(e, pack2(y.y, y.y), rq);
    }
    float P, nT, R, nQ;
    unpack2(pt, P, nT); unpack2(rq, R, nQ);
    float2* Z = g_Z + (size_t)bc*(KX24*M12);
    if (kr < 12)
        Z[kr*M12 + ky] = make_float2(P - nQ, R + nT);        // z+ = (P+Q, R-T)
    if (kr >= 1)
        Z[(24 - kr)*M12 + ky] = make_float2(P + nQ, R - nT); // z- = (P-Q, R+T)
}

// ---------------- K3: mode mix ----------------
__global__ void k3_mix(const float* __restrict__ spec_w, int layer) {
    __shared__ float2 sZ[Bsz*CH];
    int f = blockIdx.x;
    int kxi = f / M12, ky = f % M12;
    int region = (kxi < M12) ? 0 : 1;
    int xx = (kxi < M12) ? kxi : (kxi - M12);

    int tb = threadIdx.x / CH;
    int o  = threadIdx.x % CH;
    sZ[tb*CH + o] = g_Z[((size_t)(tb*CH + o))*(KX24*M12) + f];
    __syncthreads();

    const float* Wb = spec_w + (size_t)(layer*2 + region)*CH*CH*M12*M12*2
                             + (size_t)(xx*M12 + ky)*2;
    float orr = 0.f, oii = 0.f;
#pragma unroll 4
    for (int i = 0; i < CH; i++) {
        float2 z = sZ[tb*CH + i];
        const float* wp = Wb + (size_t)(i*CH + o)*(M12*M12*2);
        float wr = wp[0], wi = wp[1];
        orr += z.x*wr - z.y*wi;
        oii += z.x*wi + z.y*wr;
    }
    g_Zm[((size_t)(tb*CH + o))*(KX24*M12) + f] = make_float2(orr, oii);
}

// ---------------- K4: inverse DFT along h; conjugate-pair u/v precombine ----------------
__global__ __launch_bounds__(256) void k4_inv_h() {
    __shared__ float2 sZm[KX24*M12];
    __shared__ ull su[12*12], sv[12*12];
    __shared__ ull sz0[12];
    int bc = blockIdx.x, tid = threadIdx.x;
    const float2* Zg = g_Zm + (size_t)bc*(KX24*M12);
    for (int t = tid; t < KX24*M12; t += 256) sZm[t] = Zg[t];
    __syncthreads();
    if (tid < 144) {
        int kr = 1 + tid/12, ky = tid % 12;
        float2 u, v;
        if (kr <= 11) {
            float2 a = sZm[kr*M12 + ky];         // kx = kr  (e^{+i th})
            float2 d = sZm[(24 - kr)*M12 + ky];  // kx = 255-kr (e^{-i th})
            u = make_float2(a.x + d.x, a.y + d.y);
            v = make_float2(d.y - a.y, a.x - d.x);
        } else {                                 // kr == 12: only kx = 255-12 (e^{-i th})
            float2 a = sZm[12*M12 + ky];
            u = make_float2(a.x, a.y);
            v = make_float2(a.y, -a.x);
        }
        su[tid] = pack2(u.x, u.y);
        sv[tid] = pack2(v.x, v.y);
    } else if (tid < 156) {
        int ky = tid - 144;
        float2 z0 = sZm[ky];
        sz0[ky] = pack2(z0.x, z0.y);
    }
    __syncthreads();

    for (int idx = tid; idx < HH*M12; idx += 256) {
        int hh = idx / M12, ky = idx % M12;
        ull acc = sz0[ky];
#pragma unroll
        for (int kr = 1; kr <= 12; kr++) {
            float c = __ldg(&g_Ec[kr*256 + hh]);
            float s = __ldg(&g_Es[kr*256 + hh]);
            acc = ffma2(pack2(c, c), su[(kr-1)*12 + ky], acc);
            acc = ffma2(pack2(s, s), sv[(kr-1)*12 + ky], acc);
        }
        ((ull*)g_Yi)[(size_t)bc*HH*M12 + idx] = acc;
    }
}

// ---------------- K5: fused inverse-w + 1x1 conv + bias + BN stats ----------------
// Warp = 4 output channels; lane = 8 pixels. qi negated so spectral = qr*cos + (-qi)*sin.
__global__ __launch_bounds__(256, 3) void k5_invw_conv(const float* __restrict__ conv_w,
                                                       const float* __restrict__ conv_b,
                                                       int layer, int prev_bn) {
    __shared__ float  sH[32*260];
    __shared__ float  sQr[12*32], sQi[12*32];
    __shared__ float4 sCwT[32*8];
    __shared__ float  sCb[CH], ssum[CH], ssq[CH], sScl[CH], sShf[CH];

    int bb = blockIdx.x / HH, hh = blockIdx.x % HH;
    int tid = threadIdx.x;

    if (tid < CH) {
        sCb[tid]  = conv_b[layer*CH + tid];
        ssum[tid] = 0.f; ssq[tid] = 0.f;
        sScl[tid] = prev_bn ? g_scale[tid] : 1.f;
        sShf[tid] = prev_bn ? g_shift[tid] : 0.f;
    }
    {
        int og = tid >> 5, c = tid & 31;
        const float* cw = conv_w + layer*CH*CH;
        sCwT[c*8 + og] = make_float4(cw[(og*4+0)*CH + c], cw[(og*4+1)*CH + c],
                                     cw[(og*4+2)*CH + c], cw[(og*4+3)*CH + c]);
    }
    __syncthreads();

    const float* src = prev_bn ? g_t : g_h;
    for (int t = tid; t < 32*64; t += 256) {
        int c = t >> 6, seg = t & 63;
        float4 v = *(const float4*)&src[((size_t)(bb*CH + c)*HH + hh)*WP + seg*4];
        if (prev_bn) {
            float scl = sScl[c], shf = sShf[c];
            v.x = fmaxf(v.x*scl + shf, 0.f);
            v.y = fmaxf(v.y*scl + shf, 0.f);
            v.z = fmaxf(v.z*scl + shf, 0.f);
            v.w = fmaxf(v.w*scl + shf, 0.f);
        }
        if (seg == 63) v.w = 0.f;
        *(float4*)&sH[c*260 + seg*4] = v;
    }
    const float dsc = 1.0f / 65025.0f;
    for (int t = tid; t < 12*32; t += 256) {
        int ky = t >> 5, c = t & 31;
        float2 y = g_Yi[((size_t)(bb*CH + c)*HH + hh)*M12 + ky];
        float f = (ky == 0) ? dsc : 2.0f*dsc;
        sQr[ky*32 + c] =  y.x * f;
        sQi[ky*32 + c] = -y.y * f;      // negated: Re(Y e^{+i th}) = Yr cos - Yi sin
    }
    __syncthreads();

    int og = tid >> 5, lane = tid & 31;
    int pA = lane*4, pB = 128 + lane*4;

    ull acc[4][4];
#pragma unroll
    for (int j = 0; j < 4; j++) {
        float cb = sCb[og*4 + j];
        ull cb2 = pack2(cb, cb);
        acc[j][0] = cb2; acc[j][1] = cb2; acc[j][2] = cb2; acc[j][3] = cb2;
    }

#pragma unroll
    for (int k = 0; k < 12; k++) {
        float4 cA = __ldg((const float4*)&g_Ec[k*256 + pA]);
        float4 cB = __ldg((const float4*)&g_Ec[k*256 + pB]);
        float4 sA = __ldg((const float4*)&g_Es[k*256 + pA]);
        float4 sB = __ldg((const float4*)&g_Es[k*256 + pB]);
        ull cA0 = pack2(cA.x, cA.y), cA1 = pack2(cA.z, cA.w);
        ull cB0 = pack2(cB.x, cB.y), cB1 = pack2(cB.z, cB.w);
        ull sA0 = pack2(sA.x, sA.y), sA1 = pack2(sA.z, sA.w);
        ull sB0 = pack2(sB.x, sB.y), sB1 = pack2(sB.z, sB.w);
        float4 qr = *(const float4*)&sQr[k*32 + og*4];
        float4 qi = *(const float4*)&sQi[k*32 + og*4];
        const float* qrp = (const float*)&qr;
        const float* qip = (const float*)&qi;
#pragma unroll
        for (int j = 0; j < 4; j++) {
            ull qrd = pack2(qrp[j], qrp[j]);
            ull qid = pack2(qip[j], qip[j]);
            acc[j][0] = ffma2(cA0, qrd, acc[j][0]); acc[j][0] = ffma2(sA0, qid, acc[j][0]);
            acc[j][1] = ffma2(cA1, qrd, acc[j][1]); acc[j][1] = ffma2(sA1, qid, acc[j][1]);
            acc[j][2] = ffma2(cB0, qrd, acc[j][2]); acc[j][2] = ffma2(sB0, qid, acc[j][2]);
            acc[j][3] = ffma2(cB1, qrd, acc[j][3]); acc[j][3] = ffma2(sB1, qid, acc[j][3]);
        }
    }

#pragma unroll 4
    for (int c = 0; c < 32; c++) {
        const float* hrow = sH + c*260;
        ulonglong2 hA = *(const ulonglong2*)&hrow[pA];
        ulonglong2 hB = *(const ulonglong2*)&hrow[pB];
        float4 w4 = sCwT[c*8 + og];
        const float* wp = (const float*)&w4;
#pragma unroll
        for (int j = 0; j < 4; j++) {
            ull wd = pack2(wp[j], wp[j]);
            acc[j][0] = ffma2(hA.x, wd, acc[j][0]);
            acc[j][1] = ffma2(hA.y, wd, acc[j][1]);
            acc[j][2] = ffma2(hB.x, wd, acc[j][2]);
            acc[j][3] = ffma2(hB.y, wd, acc[j][3]);
        }
    }

    if (lane == 31) {            // pixel 255 is padding
#pragma unroll
        for (int j = 0; j < 4; j++) {
            float lo, hi; unpack2(acc[j][3], lo, hi);
            acc[j][3] = pack2(lo, 0.f);
        }
    }

#pragma unroll
    for (int j = 0; j < 4; j++) {
        int o = og*4 + j;
        float* orow = g_t + ((size_t)(bb*CH + o)*HH + hh)*WP;
        *(ulonglong2*)&orow[pA] = make_ulonglong2(acc[j][0], acc[j][1]);
        *(ulonglong2*)&orow[pB] = make_ulonglong2(acc[j][2], acc[j][3]);
        ull s2 = fadd2(fadd2(acc[j][0], acc[j][1]), fadd2(acc[j][2], acc[j][3]));
        ull q2 = ffma2(acc[j][0], acc[j][0], ffma2(acc[j][1], acc[j][1],
                  ffma2(acc[j][2], acc[j][2], ffma2(acc[j][3], acc[j][3], 0ULL))));
        float u1, u2; unpack2(s2, u1, u2); float ls = u1 + u2;
        unpack2(q2, u1, u2); float lq = u1 + u2;
        atomicAdd(&ssum[o], ls);
        atomicAdd(&ssq[o],  lq);
    }
    __syncthreads();
    if (tid < CH) {
        atomicAdd(&g_sum[tid],   ssum[tid]);
        atomicAdd(&g_sumsq[tid], ssq[tid]);
    }
}

// ---------------- K6: finalize BN stats ----------------
__global__ void k6_bn(const float* __restrict__ bn_g, const float* __restrict__ bn_b,
                      int layer) {
    int c = threadIdx.x;
    if (c < CH) {
        const float N = (float)Bsz * (float)NPIX;
        float mean = g_sum[c] / N;
        float var  = g_sumsq[c] / N - mean*mean;
        float inv  = rsqrtf(var + BN_EPS);
        float gg = bn_g[layer*CH + c], bb = bn_b[layer*CH + c];
        g_scale[c] = gg * inv;
        g_shift[c] = bb - gg * inv * mean;
        g_sum[c] = 0.f; g_sumsq[c] = 0.f;
    }
}

// ---------------- K8: head ----------------
__global__ __launch_bounds__(128) void k8_head(const float* __restrict__ fc1_w,
                                               const float* __restrict__ fc1_b,
                                               const float* __restrict__ fc2_w,
                                               const float* __restrict__ fc2_b,
                                               float* __restrict__ out) {
    __shared__ float W1T[128][36];
    __shared__ float b1[128];
    __shared__ float W2[128];
    __shared__ float sc[CH], sh[CH];

    for (int t = threadIdx.x; t < CH*128; t += 128) {
        int c = t >> 7, d = t & 127;
        W1T[d][c] = fc1_w[t];
    }
    b1[threadIdx.x] = fc1_b[threadIdx.x];
    W2[threadIdx.x] = fc2_w[threadIdx.x];
    if (threadIdx.x < CH) { sc[threadIdx.x] = g_scale[threadIdx.x]; sh[threadIdx.x] = g_shift[threadIdx.x]; }
    __syncthreads();

    int p = blockIdx.x * 128 + threadIdx.x;
    if (p >= Bsz*S*S) return;
    int b = p >> 14, q = p & 16383;
    int ii = q >> 7, jj = q & 127;
    int i = ii + (S-1), j = jj + (S-1);

    float in[CH];
#pragma unroll
    for (int c = 0; c < CH; c++)
        in[c] = g_t[((size_t)(b*CH + c)*HH + i)*WP + j] * sc[c] + sh[c];

    float acc = fc2_b[0];
#pragma unroll 2
    for (int d = 0; d < 128; d++) {
        float a = b1[d];
#pragma unroll
        for (int c4 = 0; c4 < CH; c4 += 4) {
            float4 w4 = *(const float4*)&W1T[d][c4];
            a += in[c4]*w4.x + in[c4+1]*w4.y + in[c4+2]*w4.z + in[c4+3]*w4.w;
        }
        a = fmaxf(a, 0.f);
        acc += a * W2[d];
    }
#pragma unroll
    for (int c3 = 0; c3 < DCH; c3++)
        out[((b*DCH + c3)*S + ii)*S + jj] = acc;
}

// ---------------- launch ----------------
extern "C" void kernel_launch(void* const* d_in, const int* in_sizes, int n_in,
                              void* d_out, int out_size) {
    const float* x      = (const float*)d_in[0];
    const float* fc0_w  = (const float*)d_in[1];
    const float* fc0_b  = (const float*)d_in[2];
    const float* spec_w = (const float*)d_in[3];
    const float* conv_w = (const float*)d_in[4];
    const float* conv_b = (const float*)d_in[5];
    const float* bn_g   = (const float*)d_in[6];
    const float* bn_b   = (const float*)d_in[7];
    const float* fc1_w  = (const float*)d_in[8];
    const float* fc1_b  = (const float*)d_in[9];
    const float* fc2_w  = (const float*)d_in[10];
    const float* fc2_b  = (const float*)d_in[11];
    float* out = (float*)d_out;

    k_init<<<13, 256>>>();
    k0_fc0<<<(Bsz*NPIX + 255)/256, 256>>>(x, fc0_w, fc0_b);

    for (int layer = 0; layer < 4; layer++) {
        int prev_bn = (layer > 0) ? 1 : 0;
        k1_fwd_w<<<ROWS/32, 192>>>(prev_bn);
        k2_fwd_h<<<Bsz*CH, 160>>>();
        k3_mix<<<KX24*M12, Bsz*CH>>>(spec_w, layer);
        k4_inv_h<<<Bsz*CH, 256>>>();
        k5_invw_conv<<<Bsz*HH, 256>>>(conv_w, conv_b, layer, prev_bn);
        k6_bn<<<1, 32>>>(bn_g, bn_b, layer);
    }
    k8_head<<<(Bsz*S*S + 127)/128, 128>>>(fc1_w, fc1_b, fc2_w, fc2_b, out);
}